// round 1
// baseline (speedup 1.0000x reference)
#include <cuda_runtime.h>

#define BS_ 1024
#define DS_ 128
#define DM_ 256
#define NH_ 4
#define DH_ 32
#define T_ 8
#define NL_ 2
#define DECAY_F 0.6065306597126334f
#define SCALE_F 0.17677669529663687f

// ---------------- device state (scratch; no allocations allowed) ----------------
__device__ __align__(16) float g_tok[BS_*DM_];          // embedding (layer0 input, all t)
__device__ __align__(16) float g_x[BS_*DM_];            // layer1 input (layer0 out spikes)
__device__ __align__(16) float g_h[NL_][BS_*DS_];       // hidden spikes (carry)
__device__ __align__(16) float g_sv[NL_][BS_*DS_];      // state LIF membrane
__device__ __align__(16) float g_ov[NL_][BS_*DM_];      // output LIF membrane
__device__ __align__(16) float g_qst[BS_*2*DS_];        // cols 0..127 = q, 128..255 = st
__device__ __align__(16) float g_kv[BS_*2*DS_];         // cols 0..127 = k, 128..255 = v
__device__ __align__(16) float g_att[BS_*DS_];
__device__ __align__(16) float g_tsum[BS_*DM_];         // time-mean accumulator (already /8)
__device__ __align__(16) float g_WqA[NL_][2*DS_*DS_];   // packed [Wq; A]
__device__ float g_bqz[NL_][2*DS_];                     // packed [bq; 0]
__device__ float g_ts[NL_], g_to[NL_];                  // scalar thresholds
__device__ unsigned int g_cnt1, g_cnt2;                 // integer spike counters

// ---------------- init / pack / embed ----------------
__global__ void init_kernel() {
    int idx = blockIdx.x * blockDim.x + threadIdx.x;
    int stride = gridDim.x * blockDim.x;
    float* h  = &g_h[0][0];
    float* sv = &g_sv[0][0];
    float* ov = &g_ov[0][0];
    for (int i = idx; i < NL_*BS_*DS_; i += stride) { h[i] = 0.f; sv[i] = 0.f; }
    for (int i = idx; i < NL_*BS_*DM_; i += stride) { ov[i] = 0.f; }
    for (int i = idx; i < BS_*DM_;     i += stride) { g_tsum[i] = 0.f; }
    if (idx == 0) {
        g_ts[0] = g_ts[1] = 1.0f;
        g_to[0] = g_to[1] = 1.0f;
        g_cnt1 = 0u; g_cnt2 = 0u;
    }
}

__global__ void pack_kernel(const float* __restrict__ Wq,
                            const float* __restrict__ Amat,
                            const float* __restrict__ bq) {
    int idx = blockIdx.x * blockDim.x + threadIdx.x;
    int stride = gridDim.x * blockDim.x;
    const int tot = NL_*2*DS_*DS_;
    for (int i = idx; i < tot; i += stride) {
        int l = i / (2*DS_*DS_);
        int rem = i % (2*DS_*DS_);
        int j = rem / DS_, k = rem % DS_;
        float v = (j < DS_) ? Wq[l*DS_*DS_ + j*DS_ + k]
                            : Amat[l*DS_*DS_ + (j-DS_)*DS_ + k];
        g_WqA[l][rem] = v;
    }
    for (int i = idx; i < NL_*2*DS_; i += stride) {
        int l = i / (2*DS_), j = i % (2*DS_);
        g_bqz[l][j] = (j < DS_) ? bq[l*DS_ + j] : 0.f;
    }
}

__global__ void embed_kernel(const int* __restrict__ ids, const float* __restrict__ emb) {
    int row = blockIdx.x;          // 0..1023
    int j = threadIdx.x;           // 0..255
    g_tok[row*DM_ + j] = emb[(size_t)ids[row]*DM_ + j];
}

// ---------------- shared 64x64 fp32 GEMM core (inner-product W[N][K]) ----------------
__device__ __forceinline__ void gemm64(const float* __restrict__ in,
                                       const float* __restrict__ W,
                                       int K, int row0, int col0,
                                       float acc[4][4]) {
    __shared__ __align__(16) float As[16][64];
    __shared__ __align__(16) float Ws[16][64];
    const int tid = threadIdx.x;
    const int lr = tid >> 2;            // 0..63
    const int lk = (tid & 3) << 2;      // 0,4,8,12
    const int tx = tid & 15;
    const int ty = tid >> 4;
    for (int k0 = 0; k0 < K; k0 += 16) {
        float4 av = *reinterpret_cast<const float4*>(in + (size_t)(row0+lr)*K + k0 + lk);
        float4 wv = *reinterpret_cast<const float4*>(W  + (size_t)(col0+lr)*K + k0 + lk);
        As[lk+0][lr]=av.x; As[lk+1][lr]=av.y; As[lk+2][lr]=av.z; As[lk+3][lr]=av.w;
        Ws[lk+0][lr]=wv.x; Ws[lk+1][lr]=wv.y; Ws[lk+2][lr]=wv.z; Ws[lk+3][lr]=wv.w;
        __syncthreads();
#pragma unroll
        for (int kk = 0; kk < 16; kk++) {
            float4 a = *reinterpret_cast<const float4*>(&As[kk][ty*4]);
            float4 w = *reinterpret_cast<const float4*>(&Ws[kk][tx*4]);
            acc[0][0]+=a.x*w.x; acc[0][1]+=a.x*w.y; acc[0][2]+=a.x*w.z; acc[0][3]+=a.x*w.w;
            acc[1][0]+=a.y*w.x; acc[1][1]+=a.y*w.y; acc[1][2]+=a.y*w.z; acc[1][3]+=a.y*w.w;
            acc[2][0]+=a.z*w.x; acc[2][1]+=a.z*w.y; acc[2][2]+=a.z*w.z; acc[2][3]+=a.z*w.w;
            acc[3][0]+=a.w*w.x; acc[3][1]+=a.w*w.y; acc[3][2]+=a.w*w.z; acc[3][3]+=a.w*w.w;
        }
        __syncthreads();
    }
}

// ---------------- qst + kv GEMMs fused via gridDim.z ----------------
__global__ void k_ab(int l, const float* __restrict__ Wkv, const float* __restrict__ bkv) {
    const float* in; const float* W; const float* bias; float* out; int K;
    if (blockIdx.z == 0) {
        in = g_h[l]; W = g_WqA[l]; bias = g_bqz[l]; out = g_qst; K = DS_;
    } else {
        in = (l == 0) ? g_tok : g_x;
        W = Wkv + (size_t)l*2*DS_*DM_; bias = bkv + l*2*DS_; out = g_kv; K = DM_;
    }
    float acc[4][4] = {};
    int row0 = blockIdx.y*64, col0 = blockIdx.x*64;
    gemm64(in, W, K, row0, col0, acc);
    int tx = threadIdx.x & 15, ty = threadIdx.x >> 4;
#pragma unroll
    for (int i = 0; i < 4; i++) {
        int r = row0 + ty*4 + i;
#pragma unroll
        for (int j = 0; j < 4; j++) {
            int c = col0 + tx*4 + j;
            out[r*(2*DS_) + c] = acc[i][j] + bias[c];
        }
    }
}

// ---------------- flash attention over all 1024 positions, 4 heads ----------------
__global__ void k_attn() {
    __shared__ __align__(16) float Qs[32][36];
    __shared__ __align__(16) float Ks[64][36];
    __shared__ __align__(16) float Vs[64][36];
    __shared__ float Ps[32][68];
    const int tid = threadIdx.x;         // 256 threads
    const int head = blockIdx.y;
    const int q0 = blockIdx.x * 32;

    for (int i = tid; i < 32*32; i += 256) {
        int r = i >> 5, d = i & 31;
        Qs[r][d] = g_qst[(q0+r)*(2*DS_) + head*DH_ + d];
    }
    const int r = tid >> 3;              // query row within tile (0..31)
    const int lane8 = tid & 7;           // 8 lanes per row, same warp
    const int d0 = lane8 * 4;            // 4 output dims per lane

    float m = -INFINITY, lsum = 0.f;
    float o0 = 0.f, o1 = 0.f, o2 = 0.f, o3 = 0.f;

    for (int kt = 0; kt < 16; kt++) {
        __syncthreads();
        for (int i = tid; i < 64*32; i += 256) {
            int kr = i >> 5, d = i & 31;
            int key = kt*64 + kr;
            Ks[kr][d] = g_kv[key*(2*DS_) + head*DH_ + d];
            Vs[kr][d] = g_kv[key*(2*DS_) + DS_ + head*DH_ + d];
        }
        __syncthreads();

        float s[8];
#pragma unroll
        for (int kk = 0; kk < 8; kk++) s[kk] = 0.f;
#pragma unroll
        for (int d4 = 0; d4 < 8; d4++) {
            float4 q = *reinterpret_cast<const float4*>(&Qs[r][d4*4]);
#pragma unroll
            for (int kk = 0; kk < 8; kk++) {
                float4 k4 = *reinterpret_cast<const float4*>(&Ks[lane8 + kk*8][d4*4]);
                s[kk] += q.x*k4.x + q.y*k4.y + q.z*k4.z + q.w*k4.w;
            }
        }
        float tmax = -INFINITY;
#pragma unroll
        for (int kk = 0; kk < 8; kk++) { s[kk] *= SCALE_F; tmax = fmaxf(tmax, s[kk]); }
#pragma unroll
        for (int off = 4; off > 0; off >>= 1)
            tmax = fmaxf(tmax, __shfl_xor_sync(0xffffffffu, tmax, off));
        float mnew = fmaxf(m, tmax);
        float corr = expf(m - mnew);        // exp(-inf)=0 on first tile
        float psum = 0.f;
#pragma unroll
        for (int kk = 0; kk < 8; kk++) {
            float p = expf(s[kk] - mnew);
            Ps[r][lane8 + kk*8] = p;
            psum += p;
        }
#pragma unroll
        for (int off = 4; off > 0; off >>= 1)
            psum += __shfl_xor_sync(0xffffffffu, psum, off);
        lsum = lsum * corr + psum;
        m = mnew;
        o0 *= corr; o1 *= corr; o2 *= corr; o3 *= corr;
        __syncwarp();
#pragma unroll
        for (int key = 0; key < 64; key++) {
            float p = Ps[r][key];
            float4 vv = *reinterpret_cast<const float4*>(&Vs[key][d0]);
            o0 += p*vv.x; o1 += p*vv.y; o2 += p*vv.z; o3 += p*vv.w;
        }
    }
    float inv = 1.f / lsum;
    float* dst = &g_att[(q0+r)*DS_ + head*DH_ + d0];
    dst[0] = o0*inv; dst[1] = o1*inv; dst[2] = o2*inv; dst[3] = o3*inv;
}

// ---------------- upd = st + att@Wo.T + bo ; LIF1 ----------------
__global__ void k_d(int l, const float* __restrict__ Wo, const float* __restrict__ bo) {
    float acc[4][4] = {};
    int row0 = blockIdx.y*64, col0 = blockIdx.x*64;
    gemm64(g_att, Wo + (size_t)l*DS_*DS_, DS_, row0, col0, acc);
    int tid = threadIdx.x, tx = tid & 15, ty = tid >> 4;
    float thr = g_ts[l];
    int spikes = 0;
#pragma unroll
    for (int i = 0; i < 4; i++) {
        int r = row0 + ty*4 + i;
#pragma unroll
        for (int j = 0; j < 4; j++) {
            int c = col0 + tx*4 + j;
            float upd = acc[i][j] + bo[l*DS_ + c] + g_qst[r*(2*DS_) + DS_ + c];
            float v = g_sv[l][r*DS_ + c] * DECAY_F + upd;
            float sp = (v >= thr) ? 1.f : 0.f;
            g_h[l][r*DS_ + c] = sp;
            g_sv[l][r*DS_ + c] = v * (1.f - sp);
            spikes += (v >= thr) ? 1 : 0;
        }
    }
    __shared__ int sred[256];
    sred[tid] = spikes; __syncthreads();
    for (int s = 128; s > 0; s >>= 1) { if (tid < s) sred[tid] += sred[tid+s]; __syncthreads(); }
    if (tid == 0) atomicAdd(&g_cnt1, (unsigned)sred[0]);
}

// ---------------- out_pot = h2@C.T ; LIF2 ; feed next layer / time-mean ----------------
__global__ void k_e(int l, const float* __restrict__ Cmat) {
    float acc[4][4] = {};
    int row0 = blockIdx.y*64, col0 = blockIdx.x*64;
    gemm64(g_h[l], Cmat + (size_t)l*DM_*DS_, DS_, row0, col0, acc);
    int tid = threadIdx.x, tx = tid & 15, ty = tid >> 4;
    float thr = g_to[l];
    int spikes = 0;
#pragma unroll
    for (int i = 0; i < 4; i++) {
        int r = row0 + ty*4 + i;
#pragma unroll
        for (int j = 0; j < 4; j++) {
            int c = col0 + tx*4 + j;
            float v = g_ov[l][r*DM_ + c] * DECAY_F + acc[i][j];
            float sp = (v >= thr) ? 1.f : 0.f;
            g_ov[l][r*DM_ + c] = v * (1.f - sp);
            if (l == 0) g_x[r*DM_ + c] = sp;
            else        g_tsum[r*DM_ + c] += sp * 0.125f;
            spikes += (v >= thr) ? 1 : 0;
        }
    }
    __shared__ int sred[256];
    sred[tid] = spikes; __syncthreads();
    for (int s = 128; s > 0; s >>= 1) { if (tid < s) sred[tid] += sred[tid+s]; __syncthreads(); }
    if (tid == 0) atomicAdd(&g_cnt2, (unsigned)sred[0]);
}

// ---------------- threshold update (exact: integer counts, pow2 divisors) ----------------
__global__ void k_thr(int l) {
    float e1 = (float)g_cnt1 / (float)(BS_*DS_) - 0.02f;
    g_ts[l] = fmaxf(g_ts[l] + 0.1f*e1, 0.5f);
    float e2 = (float)g_cnt2 / (float)(BS_*DM_) - 0.02f;
    g_to[l] = fmaxf(g_to[l] + 0.1f*e2, 0.5f);
    g_cnt1 = 0u; g_cnt2 = 0u;
}

// ---------------- logits = tsum @ Wout.T + bout  (1024 x 32000 x 256) ----------------
__global__ void __launch_bounds__(256, 2)
k_logits(const float* __restrict__ Wout, const float* __restrict__ bout,
         float* __restrict__ out) {
    __shared__ __align__(16) float As[16][128];
    __shared__ __align__(16) float Ws[16][128];
    const int tid = threadIdx.x;
    const int row0 = blockIdx.y * 128;
    const int col0 = blockIdx.x * 128;
    const int lr = tid >> 1;             // 0..127
    const int lk = (tid & 1) << 3;       // 0 or 8
    const int tx = tid & 15, ty = tid >> 4;
    float acc[8][8] = {};
    for (int k0 = 0; k0 < 256; k0 += 16) {
        float4 a0 = *reinterpret_cast<const float4*>(&g_tsum[(row0+lr)*256 + k0 + lk]);
        float4 a1 = *reinterpret_cast<const float4*>(&g_tsum[(row0+lr)*256 + k0 + lk + 4]);
        float4 w0 = *reinterpret_cast<const float4*>(&Wout[(size_t)(col0+lr)*256 + k0 + lk]);
        float4 w1 = *reinterpret_cast<const float4*>(&Wout[(size_t)(col0+lr)*256 + k0 + lk + 4]);
        As[lk+0][lr]=a0.x; As[lk+1][lr]=a0.y; As[lk+2][lr]=a0.z; As[lk+3][lr]=a0.w;
        As[lk+4][lr]=a1.x; As[lk+5][lr]=a1.y; As[lk+6][lr]=a1.z; As[lk+7][lr]=a1.w;
        Ws[lk+0][lr]=w0.x; Ws[lk+1][lr]=w0.y; Ws[lk+2][lr]=w0.z; Ws[lk+3][lr]=w0.w;
        Ws[lk+4][lr]=w1.x; Ws[lk+5][lr]=w1.y; Ws[lk+6][lr]=w1.z; Ws[lk+7][lr]=w1.w;
        __syncthreads();
#pragma unroll
        for (int kk = 0; kk < 16; kk++) {
            float a[8], w[8];
            float4 ta = *reinterpret_cast<const float4*>(&As[kk][ty*8]);
            float4 tb = *reinterpret_cast<const float4*>(&As[kk][ty*8+4]);
            a[0]=ta.x; a[1]=ta.y; a[2]=ta.z; a[3]=ta.w;
            a[4]=tb.x; a[5]=tb.y; a[6]=tb.z; a[7]=tb.w;
            float4 tw = *reinterpret_cast<const float4*>(&Ws[kk][tx*8]);
            float4 tw2 = *reinterpret_cast<const float4*>(&Ws[kk][tx*8+4]);
            w[0]=tw.x; w[1]=tw.y; w[2]=tw.z; w[3]=tw.w;
            w[4]=tw2.x; w[5]=tw2.y; w[6]=tw2.z; w[7]=tw2.w;
#pragma unroll
            for (int i = 0; i < 8; i++)
#pragma unroll
                for (int j = 0; j < 8; j++)
                    acc[i][j] += a[i] * w[j];
        }
        __syncthreads();
    }
#pragma unroll
    for (int i = 0; i < 8; i++) {
        int r = row0 + ty*8 + i;
        float4 v0, v1;
        int cbase = col0 + tx*8;
        v0.x = acc[i][0] + bout[cbase+0];
        v0.y = acc[i][1] + bout[cbase+1];
        v0.z = acc[i][2] + bout[cbase+2];
        v0.w = acc[i][3] + bout[cbase+3];
        v1.x = acc[i][4] + bout[cbase+4];
        v1.y = acc[i][5] + bout[cbase+5];
        v1.z = acc[i][6] + bout[cbase+6];
        v1.w = acc[i][7] + bout[cbase+7];
        *reinterpret_cast<float4*>(&out[(size_t)r*32000 + cbase]) = v0;
        *reinterpret_cast<float4*>(&out[(size_t)r*32000 + cbase + 4]) = v1;
    }
}

// ---------------- launch ----------------
extern "C" void kernel_launch(void* const* d_in, const int* in_sizes, int n_in,
                              void* d_out, int out_size) {
    const int*   ids  = (const int*)d_in[0];
    const float* emb  = (const float*)d_in[1];
    const float* Amat = (const float*)d_in[2];
    const float* Cmat = (const float*)d_in[3];
    const float* Wq   = (const float*)d_in[4];
    const float* bq   = (const float*)d_in[5];
    const float* Wkv  = (const float*)d_in[6];
    const float* bkv  = (const float*)d_in[7];
    const float* Wo   = (const float*)d_in[8];
    const float* bo   = (const float*)d_in[9];
    const float* Wout = (const float*)d_in[10];
    const float* bout = (const float*)d_in[11];
    float* out = (float*)d_out;

    init_kernel<<<256, 256>>>();
    pack_kernel<<<256, 256>>>(Wq, Amat, bq);
    embed_kernel<<<1024, 256>>>(ids, emb);

    for (int t = 0; t < T_; t++) {
        for (int l = 0; l < NL_; l++) {
            k_ab  <<<dim3(4, 16, 2), 256>>>(l, Wkv, bkv);
            k_attn<<<dim3(32, 4),    256>>>();
            k_d   <<<dim3(2, 16),    256>>>(l, Wo, bo);
            k_e   <<<dim3(4, 16),    256>>>(l, Cmat);
            k_thr <<<1, 1>>>(l);
        }
    }
    k_logits<<<dim3(250, 8), 256>>>(Wout, bout, out);
}

// round 3
// speedup vs baseline: 1.0623x; 1.0623x over previous
#include <cuda_runtime.h>
#include <cuda_bf16.h>
#include <mma.h>
using namespace nvcuda;

#define BS_ 1024
#define DS_ 128
#define DM_ 256
#define NH_ 4
#define DH_ 32
#define T_ 8
#define NL_ 2
#define VOC_ 32000
#define DECAY_F 0.6065306597126334f
#define SCALE_F 0.17677669529663687f

// ---------------- device state ----------------
__device__ __align__(16) float g_tok[BS_*DM_];
__device__ __align__(16) float g_x[BS_*DM_];
__device__ __align__(16) float g_h[NL_][BS_*DS_];
__device__ __align__(16) float g_sv[NL_][BS_*DS_];
__device__ __align__(16) float g_ov[NL_][BS_*DM_];
__device__ __align__(16) float g_qst[BS_*2*DS_];
__device__ __align__(16) float g_kv[BS_*2*DS_];
__device__ __align__(16) float g_att[BS_*DS_];
__device__ __align__(16) float g_tsum[BS_*DM_];
__device__ __align__(16) float g_WqA[NL_][2*DS_*DS_];
__device__ float g_bqz[NL_][2*DS_];
__device__ float g_ts[NL_], g_to[NL_];
__device__ unsigned int g_cnt1, g_cnt2;

// bf16 split storage for logits
__device__ __align__(16) __nv_bfloat16 g_Abf[BS_*DM_];
__device__ __align__(16) __nv_bfloat16 g_Whi[(size_t)VOC_*DM_];
__device__ __align__(16) __nv_bfloat16 g_Wlo[(size_t)VOC_*DM_];
__device__ __align__(16) __nv_bfloat16 g_Aext[BS_*32];
__device__ __align__(16) __nv_bfloat16 g_Bext[(size_t)VOC_*32];

// ---------------- init / pack / embed / convert ----------------
__global__ void init_kernel() {
    int idx = blockIdx.x * blockDim.x + threadIdx.x;
    int stride = gridDim.x * blockDim.x;
    float* h  = &g_h[0][0];
    float* sv = &g_sv[0][0];
    float* ov = &g_ov[0][0];
    for (int i = idx; i < NL_*BS_*DS_; i += stride) { h[i] = 0.f; sv[i] = 0.f; }
    for (int i = idx; i < NL_*BS_*DM_; i += stride) { ov[i] = 0.f; }
    for (int i = idx; i < BS_*DM_;     i += stride) { g_tsum[i] = 0.f; }
    for (int i = idx; i < BS_*32;      i += stride) {
        int c = i & 31;
        g_Aext[i] = __float2bfloat16((c < 2) ? 1.f : 0.f);
    }
    if (idx == 0) {
        g_ts[0] = g_ts[1] = 1.0f;
        g_to[0] = g_to[1] = 1.0f;
        g_cnt1 = 0u; g_cnt2 = 0u;
    }
}

__global__ void pack_kernel(const float* __restrict__ Wq,
                            const float* __restrict__ Amat,
                            const float* __restrict__ bq) {
    int idx = blockIdx.x * blockDim.x + threadIdx.x;
    int stride = gridDim.x * blockDim.x;
    const int tot = NL_*2*DS_*DS_;
    for (int i = idx; i < tot; i += stride) {
        int l = i / (2*DS_*DS_);
        int rem = i % (2*DS_*DS_);
        int j = rem / DS_, k = rem % DS_;
        float v = (j < DS_) ? Wq[l*DS_*DS_ + j*DS_ + k]
                            : Amat[l*DS_*DS_ + (j-DS_)*DS_ + k];
        g_WqA[l][rem] = v;
    }
    for (int i = idx; i < NL_*2*DS_; i += stride) {
        int l = i / (2*DS_), j = i % (2*DS_);
        g_bqz[l][j] = (j < DS_) ? bq[l*DS_ + j] : 0.f;
    }
}

__global__ void embed_kernel(const int* __restrict__ ids, const float* __restrict__ emb) {
    int row = blockIdx.x;
    int j = threadIdx.x;
    g_tok[row*DM_ + j] = emb[(size_t)ids[row]*DM_ + j];
}

__global__ void conv_w_kernel(const float* __restrict__ Wout, const float* __restrict__ bout) {
    int idx = blockIdx.x * blockDim.x + threadIdx.x;
    int stride = gridDim.x * blockDim.x;
    const size_t tot = (size_t)VOC_*DM_;
    for (size_t i = idx; i < tot; i += stride) {
        float w = Wout[i];
        __nv_bfloat16 hi = __float2bfloat16(w);
        g_Whi[i] = hi;
        g_Wlo[i] = __float2bfloat16(w - __bfloat162float(hi));
    }
    const size_t tot2 = (size_t)VOC_*32;
    for (size_t i = idx; i < tot2; i += stride) {
        int n = (int)(i >> 5), c = (int)(i & 31);
        float b = bout[n];
        __nv_bfloat16 hi = __float2bfloat16(b);
        __nv_bfloat16 v;
        if (c == 0) v = hi;
        else if (c == 1) v = __float2bfloat16(b - __bfloat162float(hi));
        else v = __float2bfloat16(0.f);
        g_Bext[i] = v;
    }
}

__global__ void conv_a_kernel() {
    int i = blockIdx.x * blockDim.x + threadIdx.x;   // exactly BS_*DM_ threads
    g_Abf[i] = __float2bfloat16(g_tsum[i]);          // k/8 values: exact
}

// ---------------- qst + kv GEMMs (64x64 tiles, 512 threads) ----------------
__global__ void __launch_bounds__(512)
k_ab(int l, const float* __restrict__ Wkv, const float* __restrict__ bkv) {
    const float* in; const float* W; const float* bias; float* out; int K;
    if (blockIdx.z == 0) {
        in = g_h[l]; W = g_WqA[l]; bias = g_bqz[l]; out = g_qst; K = DS_;
    } else {
        in = (l == 0) ? g_tok : g_x;
        W = Wkv + (size_t)l*2*DS_*DM_; bias = bkv + l*2*DS_; out = g_kv; K = DM_;
    }
    __shared__ __align__(16) float As[16][64];
    __shared__ __align__(16) float Ws[16][64];
    const int tid = threadIdx.x;
    const int row0 = blockIdx.y*64, col0 = blockIdx.x*64;
    const int ty = tid >> 4;          // 0..31 -> 2 rows
    const int tx = tid & 15;          // 4 cols
    float acc[2][4] = {};
    for (int k0 = 0; k0 < K; k0 += 16) {
        if (tid < 256) {
            int lr = tid >> 2, lk = (tid & 3) << 2;
            float4 av = *reinterpret_cast<const float4*>(in + (size_t)(row0+lr)*K + k0 + lk);
            As[lk+0][lr]=av.x; As[lk+1][lr]=av.y; As[lk+2][lr]=av.z; As[lk+3][lr]=av.w;
        } else {
            int t2 = tid - 256;
            int lr = t2 >> 2, lk = (t2 & 3) << 2;
            float4 wv = *reinterpret_cast<const float4*>(W + (size_t)(col0+lr)*K + k0 + lk);
            Ws[lk+0][lr]=wv.x; Ws[lk+1][lr]=wv.y; Ws[lk+2][lr]=wv.z; Ws[lk+3][lr]=wv.w;
        }
        __syncthreads();
#pragma unroll
        for (int kk = 0; kk < 16; kk++) {
            float2 a = *reinterpret_cast<const float2*>(&As[kk][ty*2]);
            float4 w = *reinterpret_cast<const float4*>(&Ws[kk][tx*4]);
            acc[0][0]+=a.x*w.x; acc[0][1]+=a.x*w.y; acc[0][2]+=a.x*w.z; acc[0][3]+=a.x*w.w;
            acc[1][0]+=a.y*w.x; acc[1][1]+=a.y*w.y; acc[1][2]+=a.y*w.z; acc[1][3]+=a.y*w.w;
        }
        __syncthreads();
    }
#pragma unroll
    for (int i = 0; i < 2; i++) {
        int r = row0 + ty*2 + i;
#pragma unroll
        for (int j = 0; j < 4; j++) {
            int c = col0 + tx*4 + j;
            out[r*(2*DS_) + c] = acc[i][j] + bias[c];
        }
    }
}

// ---------------- flash attention (512 threads, 32-q tile) + threshold update ----------------
__global__ void __launch_bounds__(512)
k_attn(int prev_l) {
    __shared__ __align__(16) float Qs[32][36];
    __shared__ __align__(16) float Ks[64][36];
    __shared__ __align__(16) float Vs[64][36];
    __shared__ float Ps[32][68];
    const int tid = threadIdx.x;
    const int head = blockIdx.y;
    const int q0 = blockIdx.x * 32;

    // fold threshold update of the previous (t,l) pair into this launch
    if (prev_l >= 0 && blockIdx.x == 0 && blockIdx.y == 0 && tid == 0) {
        float e1 = (float)g_cnt1 / (float)(BS_*DS_) - 0.02f;
        g_ts[prev_l] = fmaxf(g_ts[prev_l] + 0.1f*e1, 0.5f);
        float e2 = (float)g_cnt2 / (float)(BS_*DM_) - 0.02f;
        g_to[prev_l] = fmaxf(g_to[prev_l] + 0.1f*e2, 0.5f);
        g_cnt1 = 0u; g_cnt2 = 0u;
    }

    for (int i = tid; i < 32*32; i += 512) {
        int r = i >> 5, d = i & 31;
        Qs[r][d] = g_qst[(q0+r)*(2*DS_) + head*DH_ + d];
    }
    const int r = tid >> 4;            // 0..31 query row in tile
    const int lane = tid & 15;         // 16 lanes per row (same warp half)
    const int d0 = lane * 2;           // 2 output dims per lane

    float m = -INFINITY, lsum = 0.f;
    float o0 = 0.f, o1 = 0.f;

    for (int kt = 0; kt < 16; kt++) {
        __syncthreads();
        for (int i = tid; i < 64*32; i += 512) {
            int kr = i >> 5, d = i & 31;
            int key = kt*64 + kr;
            Ks[kr][d] = g_kv[key*(2*DS_) + head*DH_ + d];
            Vs[kr][d] = g_kv[key*(2*DS_) + DS_ + head*DH_ + d];
        }
        __syncthreads();

        float s[4] = {0.f, 0.f, 0.f, 0.f};
#pragma unroll
        for (int d4 = 0; d4 < 8; d4++) {
            float4 q = *reinterpret_cast<const float4*>(&Qs[r][d4*4]);
#pragma unroll
            for (int kk = 0; kk < 4; kk++) {
                float4 k4 = *reinterpret_cast<const float4*>(&Ks[lane + kk*16][d4*4]);
                s[kk] += q.x*k4.x + q.y*k4.y + q.z*k4.z + q.w*k4.w;
            }
        }
        float tmax = -INFINITY;
#pragma unroll
        for (int kk = 0; kk < 4; kk++) { s[kk] *= SCALE_F; tmax = fmaxf(tmax, s[kk]); }
#pragma unroll
        for (int off = 8; off > 0; off >>= 1)
            tmax = fmaxf(tmax, __shfl_xor_sync(0xffffffffu, tmax, off));
        float mnew = fmaxf(m, tmax);
        float corr = expf(m - mnew);
        float psum = 0.f;
#pragma unroll
        for (int kk = 0; kk < 4; kk++) {
            float p = expf(s[kk] - mnew);
            Ps[r][lane + kk*16] = p;
            psum += p;
        }
#pragma unroll
        for (int off = 8; off > 0; off >>= 1)
            psum += __shfl_xor_sync(0xffffffffu, psum, off);
        lsum = lsum * corr + psum;
        m = mnew;
        o0 *= corr; o1 *= corr;
        __syncwarp();
#pragma unroll
        for (int key = 0; key < 64; key++) {
            float p = Ps[r][key];
            float2 vv = *reinterpret_cast<const float2*>(&Vs[key][d0]);
            o0 += p*vv.x; o1 += p*vv.y;
        }
    }
    float inv = 1.f / lsum;
    float* dst = &g_att[(q0+r)*DS_ + head*DH_ + d0];
    dst[0] = o0*inv; dst[1] = o1*inv;
}

// ---------------- upd = st + att@Wo.T + bo ; LIF1  (32x32 tiles) ----------------
__global__ void __launch_bounds__(256)
k_d(int l, const float* __restrict__ Wo, const float* __restrict__ bo) {
    __shared__ __align__(16) float As[16][32];
    __shared__ __align__(16) float Ws[16][32];
    const float* W = Wo + (size_t)l*DS_*DS_;
    const int tid = threadIdx.x;
    const int row0 = blockIdx.y*32, col0 = blockIdx.x*32;
    const int ty = tid >> 4;          // 0..15 -> 2 rows
    const int tx = tid & 15;          // 2 cols
    float acc[2][2] = {};
    for (int k0 = 0; k0 < DS_; k0 += 16) {
        if (tid < 128) {
            int lr = tid >> 2, lk = (tid & 3) << 2;
            float4 av = *reinterpret_cast<const float4*>(g_att + (size_t)(row0+lr)*DS_ + k0 + lk);
            As[lk+0][lr]=av.x; As[lk+1][lr]=av.y; As[lk+2][lr]=av.z; As[lk+3][lr]=av.w;
        } else {
            int t2 = tid - 128;
            int lr = t2 >> 2, lk = (t2 & 3) << 2;
            float4 wv = *reinterpret_cast<const float4*>(W + (size_t)(col0+lr)*DS_ + k0 + lk);
            Ws[lk+0][lr]=wv.x; Ws[lk+1][lr]=wv.y; Ws[lk+2][lr]=wv.z; Ws[lk+3][lr]=wv.w;
        }
        __syncthreads();
#pragma unroll
        for (int kk = 0; kk < 16; kk++) {
            float2 a = *reinterpret_cast<const float2*>(&As[kk][ty*2]);
            float2 w = *reinterpret_cast<const float2*>(&Ws[kk][tx*2]);
            acc[0][0]+=a.x*w.x; acc[0][1]+=a.x*w.y;
            acc[1][0]+=a.y*w.x; acc[1][1]+=a.y*w.y;
        }
        __syncthreads();
    }
    float thr = g_ts[l];
    int spikes = 0;
#pragma unroll
    for (int i = 0; i < 2; i++) {
        int r = row0 + ty*2 + i;
#pragma unroll
        for (int j = 0; j < 2; j++) {
            int c = col0 + tx*2 + j;
            float upd = acc[i][j] + bo[l*DS_ + c] + g_qst[r*(2*DS_) + DS_ + c];
            float v = g_sv[l][r*DS_ + c] * DECAY_F + upd;
            float sp = (v >= thr) ? 1.f : 0.f;
            g_h[l][r*DS_ + c] = sp;
            g_sv[l][r*DS_ + c] = v * (1.f - sp);
            spikes += (v >= thr) ? 1 : 0;
        }
    }
    __shared__ int sred[256];
    sred[tid] = spikes; __syncthreads();
    for (int s = 128; s > 0; s >>= 1) { if (tid < s) sred[tid] += sred[tid+s]; __syncthreads(); }
    if (tid == 0) atomicAdd(&g_cnt1, (unsigned)sred[0]);
}

// ---------------- out_pot = h2@C.T ; LIF2  (32x64 tiles) ----------------
__global__ void __launch_bounds__(256)
k_e(int l, const float* __restrict__ Cmat) {
    __shared__ __align__(16) float As[16][32];
    __shared__ __align__(16) float Ws[16][64];
    const float* W = Cmat + (size_t)l*DM_*DS_;
    const int tid = threadIdx.x;
    const int row0 = blockIdx.y*32, col0 = blockIdx.x*64;
    const int ty = tid >> 4;          // 0..15 -> 2 rows
    const int tx = tid & 15;          // 4 cols
    float acc[2][4] = {};
    for (int k0 = 0; k0 < DS_; k0 += 16) {
        if (tid < 128) {
            int lr = tid >> 2, lk = (tid & 3) << 2;
            float4 av = *reinterpret_cast<const float4*>(g_h[l] + (size_t)(row0+lr)*DS_ + k0 + lk);
            As[lk+0][lr]=av.x; As[lk+1][lr]=av.y; As[lk+2][lr]=av.z; As[lk+3][lr]=av.w;
        }
        {
            int lr = tid >> 2, lk = (tid & 3) << 2;
            float4 wv = *reinterpret_cast<const float4*>(W + (size_t)(col0+lr)*DS_ + k0 + lk);
            Ws[lk+0][lr]=wv.x; Ws[lk+1][lr]=wv.y; Ws[lk+2][lr]=wv.z; Ws[lk+3][lr]=wv.w;
        }
        __syncthreads();
#pragma unroll
        for (int kk = 0; kk < 16; kk++) {
            float2 a = *reinterpret_cast<const float2*>(&As[kk][ty*2]);
            float4 w = *reinterpret_cast<const float4*>(&Ws[kk][tx*4]);
            acc[0][0]+=a.x*w.x; acc[0][1]+=a.x*w.y; acc[0][2]+=a.x*w.z; acc[0][3]+=a.x*w.w;
            acc[1][0]+=a.y*w.x; acc[1][1]+=a.y*w.y; acc[1][2]+=a.y*w.z; acc[1][3]+=a.y*w.w;
        }
        __syncthreads();
    }
    float thr = g_to[l];
    int spikes = 0;
#pragma unroll
    for (int i = 0; i < 2; i++) {
        int r = row0 + ty*2 + i;
#pragma unroll
        for (int j = 0; j < 4; j++) {
            int c = col0 + tx*4 + j;
            float v = g_ov[l][r*DM_ + c] * DECAY_F + acc[i][j];
            float sp = (v >= thr) ? 1.f : 0.f;
            g_ov[l][r*DM_ + c] = v * (1.f - sp);
            if (l == 0) g_x[r*DM_ + c] = sp;
            else        g_tsum[r*DM_ + c] += sp * 0.125f;
            spikes += (v >= thr) ? 1 : 0;
        }
    }
    __shared__ int sred[256];
    sred[tid] = spikes; __syncthreads();
    for (int s = 128; s > 0; s >>= 1) { if (tid < s) sred[tid] += sred[tid+s]; __syncthreads(); }
    if (tid == 0) atomicAdd(&g_cnt2, (unsigned)sred[0]);
}

// ---------------- logits via bf16 split tensor cores ----------------
// logits = Abf @ (Whi+Wlo)^T + bout, bias folded in as extra K chunk.
__global__ void __launch_bounds__(256)
k_logits_mma(float* __restrict__ out) {
    __shared__ __align__(16) __nv_bfloat16 As[128][48];
    __shared__ __align__(16) __nv_bfloat16 Bs[128][48];
    const int tid = threadIdx.x;
    const int wid = tid >> 5;
    const int wm = wid & 1;           // 2 warp rows (64 rows each)
    const int wn = wid >> 1;          // 4 warp cols (32 cols each)
    const int row0 = blockIdx.x * 128;
    const int col0 = blockIdx.y * 128;

    wmma::fragment<wmma::accumulator, 16, 16, 16, float> acc[4][2];
#pragma unroll
    for (int i = 0; i < 4; i++)
#pragma unroll
        for (int j = 0; j < 2; j++)
            wmma::fill_fragment(acc[i][j], 0.f);

    const int lr = tid >> 1;          // 0..127
    const int lh = (tid & 1) * 16;    // 0 or 16 (16 bf16 = 32B = two uint4)

    for (int c = 0; c < 17; c++) {
        const __nv_bfloat16* asrc;
        const __nv_bfloat16* bsrc;
        if (c < 16) {
            int koff = (c & 7) * 32;
            asrc = g_Abf + (size_t)(row0+lr)*DM_ + koff + lh;
            bsrc = ((c < 8) ? g_Whi : g_Wlo) + (size_t)(col0+lr)*DM_ + koff + lh;
        } else {
            asrc = g_Aext + (size_t)(row0+lr)*32 + lh;
            bsrc = g_Bext + (size_t)(col0+lr)*32 + lh;
        }
        uint4 a0 = *reinterpret_cast<const uint4*>(asrc);
        uint4 a1 = *reinterpret_cast<const uint4*>(asrc + 8);
        uint4 b0 = *reinterpret_cast<const uint4*>(bsrc);
        uint4 b1 = *reinterpret_cast<const uint4*>(bsrc + 8);
        __syncthreads();
        *reinterpret_cast<uint4*>(&As[lr][lh])     = a0;
        *reinterpret_cast<uint4*>(&As[lr][lh + 8]) = a1;
        *reinterpret_cast<uint4*>(&Bs[lr][lh])     = b0;
        *reinterpret_cast<uint4*>(&Bs[lr][lh + 8]) = b1;
        __syncthreads();
#pragma unroll
        for (int kk = 0; kk < 32; kk += 16) {
            wmma::fragment<wmma::matrix_a, 16, 16, 16, __nv_bfloat16, wmma::row_major> af[4];
            wmma::fragment<wmma::matrix_b, 16, 16, 16, __nv_bfloat16, wmma::col_major> bf[2];
#pragma unroll
            for (int i = 0; i < 4; i++)
                wmma::load_matrix_sync(af[i], &As[wm*64 + i*16][kk], 48);
#pragma unroll
            for (int j = 0; j < 2; j++)
                wmma::load_matrix_sync(bf[j], &Bs[wn*32 + j*16][kk], 48);
#pragma unroll
            for (int i = 0; i < 4; i++)
#pragma unroll
                for (int j = 0; j < 2; j++)
                    wmma::mma_sync(acc[i][j], af[i], bf[j], acc[i][j]);
        }
    }
#pragma unroll
    for (int i = 0; i < 4; i++)
#pragma unroll
        for (int j = 0; j < 2; j++) {
            size_t r = row0 + wm*64 + i*16;
            size_t cc = col0 + wn*32 + j*16;
            wmma::store_matrix_sync(&out[r*VOC_ + cc], acc[i][j], VOC_, wmma::mem_row_major);
        }
}

// ---------------- launch ----------------
extern "C" void kernel_launch(void* const* d_in, const int* in_sizes, int n_in,
                              void* d_out, int out_size) {
    const int*   ids  = (const int*)d_in[0];
    const float* emb  = (const float*)d_in[1];
    const float* Amat = (const float*)d_in[2];
    const float* Cmat = (const float*)d_in[3];
    const float* Wq   = (const float*)d_in[4];
    const float* bq   = (const float*)d_in[5];
    const float* Wkv  = (const float*)d_in[6];
    const float* bkv  = (const float*)d_in[7];
    const float* Wo   = (const float*)d_in[8];
    const float* bo   = (const float*)d_in[9];
    const float* Wout = (const float*)d_in[10];
    const float* bout = (const float*)d_in[11];
    float* out = (float*)d_out;

    init_kernel<<<256, 256>>>();
    pack_kernel<<<256, 256>>>(Wq, Amat, bq);
    embed_kernel<<<1024, 256>>>(ids, emb);
    conv_w_kernel<<<2048, 256>>>(Wout, bout);

    int prev = -1;
    for (int t = 0; t < T_; t++) {
        for (int l = 0; l < NL_; l++) {
            k_ab  <<<dim3(4, 16, 2), 512>>>(l, Wkv, bkv);
            k_attn<<<dim3(32, 4),    512>>>(prev);
            k_d   <<<dim3(4, 32),    256>>>(l, Wo, bo);
            k_e   <<<dim3(4, 32),    256>>>(l, Cmat);
            prev = l;
        }
    }
    conv_a_kernel<<<1024, 256>>>();
    k_logits_mma<<<dim3(8, 250), 256>>>(out);
}

// round 4
// speedup vs baseline: 1.3560x; 1.2765x over previous
#include <cuda_runtime.h>
#include <cuda_bf16.h>
#include <mma.h>
using namespace nvcuda;

#define BS_ 1024
#define DS_ 128
#define DM_ 256
#define NH_ 4
#define DH_ 32
#define T_ 8
#define NL_ 2
#define VOC_ 32000
#define DECAY_F 0.6065306597126334f
#define SCALE_F 0.17677669529663687f

// ---------------- device state ----------------
__device__ __align__(16) float g_tok[BS_*DM_];
__device__ __align__(16) float g_x[BS_*DM_];
__device__ __align__(16) float g_hbuf[NL_][2][BS_*DS_];   // double-buffered spikes
__device__ __align__(16) float g_sv[NL_][BS_*DS_];
__device__ __align__(16) float g_ov[NL_][BS_*DM_];
__device__ __align__(16) float g_kv0[BS_*2*DS_];          // layer-0 kv (time-invariant)
__device__ __align__(16) float g_kv[BS_*2*DS_];           // layer-1 kv (per step)
__device__ __align__(16) float g_att[BS_*DS_];
__device__ __align__(16) float g_tsum[BS_*DM_];
// transposed weights for sparse gathers
__device__ __align__(16) float g_Wqt[NL_][DS_*DS_];       // [k][d]
__device__ __align__(16) float g_At [NL_][DS_*DS_];       // [k][c]
__device__ __align__(16) float g_Ct [NL_][DS_*DM_];       // [k][c]
__device__ __align__(16) float g_Wkvt[NL_][DM_*2*DS_];    // [k][c]
__device__ float g_ts[NL_], g_to[NL_];
__device__ unsigned int g_cnt1, g_cnt2;

// bf16 split storage for logits
__device__ __align__(16) __nv_bfloat16 g_Abf[BS_*DM_];
__device__ __align__(16) __nv_bfloat16 g_Whi[(size_t)VOC_*DM_];
__device__ __align__(16) __nv_bfloat16 g_Wlo[(size_t)VOC_*DM_];
__device__ __align__(16) __nv_bfloat16 g_Aext[BS_*32];
__device__ __align__(16) __nv_bfloat16 g_Bext[(size_t)VOC_*32];

// ---------------- init / pack / embed / convert ----------------
__global__ void init_kernel() {
    int idx = blockIdx.x * blockDim.x + threadIdx.x;
    int stride = gridDim.x * blockDim.x;
    float* h  = &g_hbuf[0][0][0];
    float* sv = &g_sv[0][0];
    float* ov = &g_ov[0][0];
    for (int i = idx; i < NL_*2*BS_*DS_; i += stride) h[i] = 0.f;
    for (int i = idx; i < NL_*BS_*DS_;  i += stride) sv[i] = 0.f;
    for (int i = idx; i < NL_*BS_*DM_;  i += stride) ov[i] = 0.f;
    for (int i = idx; i < BS_*DM_;      i += stride) g_tsum[i] = 0.f;
    for (int i = idx; i < BS_*32;       i += stride) {
        int c = i & 31;
        g_Aext[i] = __float2bfloat16((c < 2) ? 1.f : 0.f);
    }
    if (idx == 0) {
        g_ts[0] = g_ts[1] = 1.0f;
        g_to[0] = g_to[1] = 1.0f;
        g_cnt1 = 0u; g_cnt2 = 0u;
    }
}

__global__ void pack_kernel(const float* __restrict__ Wq,
                            const float* __restrict__ Amat,
                            const float* __restrict__ Cmat,
                            const float* __restrict__ Wkv) {
    int idx = blockIdx.x * blockDim.x + threadIdx.x;
    int stride = gridDim.x * blockDim.x;
    for (int i = idx; i < NL_*DS_*DS_; i += stride) {
        int l = i / (DS_*DS_), rem = i % (DS_*DS_);
        int k = rem / DS_, d = rem % DS_;
        g_Wqt[l][rem] = Wq[l*DS_*DS_ + d*DS_ + k];
        g_At [l][rem] = Amat[l*DS_*DS_ + d*DS_ + k];
    }
    for (int i = idx; i < NL_*DS_*DM_; i += stride) {
        int l = i / (DS_*DM_), rem = i % (DS_*DM_);
        int k = rem / DM_, c = rem % DM_;
        g_Ct[l][rem] = Cmat[l*DM_*DS_ + c*DS_ + k];
    }
    for (int i = idx; i < NL_*DM_*2*DS_; i += stride) {
        int l = i / (DM_*2*DS_), rem = i % (DM_*2*DS_);
        int k = rem / (2*DS_), c = rem % (2*DS_);
        g_Wkvt[l][rem] = Wkv[l*2*DS_*DM_ + c*DM_ + k];
    }
}

__global__ void embed_kernel(const int* __restrict__ ids, const float* __restrict__ emb) {
    int row = blockIdx.x;
    int j = threadIdx.x;
    g_tok[row*DM_ + j] = emb[(size_t)ids[row]*DM_ + j];
}

__global__ void conv_w_kernel(const float* __restrict__ Wout, const float* __restrict__ bout) {
    int idx = blockIdx.x * blockDim.x + threadIdx.x;
    int stride = gridDim.x * blockDim.x;
    const size_t tot = (size_t)VOC_*DM_;
    for (size_t i = idx; i < tot; i += stride) {
        float w = Wout[i];
        __nv_bfloat16 hi = __float2bfloat16(w);
        g_Whi[i] = hi;
        g_Wlo[i] = __float2bfloat16(w - __bfloat162float(hi));
    }
    const size_t tot2 = (size_t)VOC_*32;
    for (size_t i = idx; i < tot2; i += stride) {
        int n = (int)(i >> 5), c = (int)(i & 31);
        float b = bout[n];
        __nv_bfloat16 hi = __float2bfloat16(b);
        __nv_bfloat16 v;
        if (c == 0) v = hi;
        else if (c == 1) v = __float2bfloat16(b - __bfloat162float(hi));
        else v = __float2bfloat16(0.f);
        g_Bext[i] = v;
    }
}

__global__ void conv_a_kernel() {
    int i = blockIdx.x * blockDim.x + threadIdx.x;
    g_Abf[i] = __float2bfloat16(g_tsum[i]);
}

// ---------------- dense kv for layer 0 (once; input = tok, K=256) ----------------
__global__ void __launch_bounds__(512)
k_kv0(const float* __restrict__ Wkv, const float* __restrict__ bkv) {
    __shared__ __align__(16) float As[16][64];
    __shared__ __align__(16) float Ws[16][64];
    const int tid = threadIdx.x;
    const int row0 = blockIdx.y*64, col0 = blockIdx.x*64;
    const int ty = tid >> 4;
    const int tx = tid & 15;
    float acc[2][4] = {};
    for (int k0 = 0; k0 < DM_; k0 += 16) {
        if (tid < 256) {
            int lr = tid >> 2, lk = (tid & 3) << 2;
            float4 av = *reinterpret_cast<const float4*>(g_tok + (size_t)(row0+lr)*DM_ + k0 + lk);
            As[lk+0][lr]=av.x; As[lk+1][lr]=av.y; As[lk+2][lr]=av.z; As[lk+3][lr]=av.w;
        } else {
            int t2 = tid - 256;
            int lr = t2 >> 2, lk = (t2 & 3) << 2;
            float4 wv = *reinterpret_cast<const float4*>(Wkv + (size_t)(col0+lr)*DM_ + k0 + lk);
            Ws[lk+0][lr]=wv.x; Ws[lk+1][lr]=wv.y; Ws[lk+2][lr]=wv.z; Ws[lk+3][lr]=wv.w;
        }
        __syncthreads();
#pragma unroll
        for (int kk = 0; kk < 16; kk++) {
            float2 a = *reinterpret_cast<const float2*>(&As[kk][ty*2]);
            float4 w = *reinterpret_cast<const float4*>(&Ws[kk][tx*4]);
            acc[0][0]+=a.x*w.x; acc[0][1]+=a.x*w.y; acc[0][2]+=a.x*w.z; acc[0][3]+=a.x*w.w;
            acc[1][0]+=a.y*w.x; acc[1][1]+=a.y*w.y; acc[1][2]+=a.y*w.z; acc[1][3]+=a.y*w.w;
        }
        __syncthreads();
    }
#pragma unroll
    for (int i = 0; i < 2; i++) {
        int r = row0 + ty*2 + i;
#pragma unroll
        for (int j = 0; j < 4; j++) {
            int c = col0 + tx*4 + j;
            g_kv0[r*(2*DS_) + c] = acc[i][j] + bkv[c];
        }
    }
}

// ---------------- sparse kv for layer 1 (input = x spikes, K=256) ----------------
__global__ void __launch_bounds__(256)
k_kv_sp(const float* __restrict__ bkv) {
    __shared__ short ql[8][256];
    __shared__ int qcnt[8];
    const int tid = threadIdx.x;
    const int row0 = blockIdx.x * 8;
    const int wrp = tid >> 5, lane = tid & 31;
    // build active list: 8 warps, 1 row each, ascending k
    {
        int r = wrp;
        int base = 0;
        const float* xr = g_x + (size_t)(row0+r)*DM_;
        for (int c4 = 0; c4 < 8; c4++) {
            float v = xr[c4*32 + lane];
            unsigned mask = __ballot_sync(0xffffffffu, v != 0.f);
            if (v != 0.f)
                ql[r][base + __popc(mask & ((1u<<lane)-1u))] = (short)(c4*32 + lane);
            base += __popc(mask);
        }
        if (lane == 0) qcnt[r] = base;
    }
    __syncthreads();
    const int c = tid;                       // 0..255
    const float* wt = g_Wkvt[1] + c;
    const float bias = bkv[2*DS_ + c];       // l=1
#pragma unroll 1
    for (int r = 0; r < 8; r++) {
        float acc = 0.f;
        int cnt = qcnt[r];
        for (int i = 0; i < cnt; i++)
            acc += wt[(int)ql[r][i] * (2*DS_)];
        g_kv[(row0+r)*(2*DS_) + c] = acc + bias;
    }
}

// ---------------- flash attention with fused sparse q-gather ----------------
__global__ void __launch_bounds__(512)
k_attn(int l, int prev_l, int par, const float* __restrict__ bq) {
    __shared__ __align__(16) float Qs[32][36];
    __shared__ __align__(16) float Ks[64][36];
    __shared__ __align__(16) float Vs[64][36];
    __shared__ float Ps[32][68];
    __shared__ short ql[32][128];
    __shared__ int qcnt[32];
    const int tid = threadIdx.x;
    const int head = blockIdx.y;
    const int q0 = blockIdx.x * 32;
    const float* kvsrc = (l == 0) ? g_kv0 : g_kv;
    const float* hsrc = g_hbuf[l][par];

    // threshold update for the previous (t,l) pair
    if (prev_l >= 0 && blockIdx.x == 0 && blockIdx.y == 0 && tid == 0) {
        float e1 = (float)g_cnt1 / (float)(BS_*DS_) - 0.02f;
        g_ts[prev_l] = fmaxf(g_ts[prev_l] + 0.1f*e1, 0.5f);
        float e2 = (float)g_cnt2 / (float)(BS_*DM_) - 0.02f;
        g_to[prev_l] = fmaxf(g_to[prev_l] + 0.1f*e2, 0.5f);
        g_cnt1 = 0u; g_cnt2 = 0u;
    }

    // build per-row active-k lists (16 warps x 2 rows)
    {
        const int wrp = tid >> 5, lane = tid & 31;
#pragma unroll
        for (int rr = 0; rr < 2; rr++) {
            int r = wrp*2 + rr;
            int base = 0;
            const float* hr = hsrc + (size_t)(q0+r)*DS_;
#pragma unroll
            for (int c4 = 0; c4 < 4; c4++) {
                float v = hr[c4*32 + lane];
                unsigned mask = __ballot_sync(0xffffffffu, v != 0.f);
                if (v != 0.f)
                    ql[r][base + __popc(mask & ((1u<<lane)-1u))] = (short)(c4*32 + lane);
                base += __popc(mask);
            }
            if (lane == 0) qcnt[r] = base;
        }
    }
    __syncthreads();

    const int r = tid >> 4;            // query row in tile (0..31)
    const int lane = tid & 15;         // 16 lanes per row
    const int d0 = lane * 2;

    // sparse q = h @ Wq.T + bq  (ascending k)
    {
        float a0 = 0.f, a1 = 0.f;
        int cnt = qcnt[r];
        const float* wt = g_Wqt[l] + head*DH_ + d0;
        for (int i = 0; i < cnt; i++) {
            float2 w = *reinterpret_cast<const float2*>(wt + (int)ql[r][i]*DS_);
            a0 += w.x; a1 += w.y;
        }
        Qs[r][d0]   = a0 + bq[l*DS_ + head*DH_ + d0];
        Qs[r][d0+1] = a1 + bq[l*DS_ + head*DH_ + d0 + 1];
    }

    float m = -INFINITY, lsum = 0.f;
    float o0a = 0.f, o0b = 0.f, o1a = 0.f, o1b = 0.f;

    for (int kt = 0; kt < 16; kt++) {
        __syncthreads();
        for (int i = tid; i < 64*32; i += 512) {
            int kr = i >> 5, d = i & 31;
            int key = kt*64 + kr;
            Ks[kr][d] = kvsrc[key*(2*DS_) + head*DH_ + d];
            Vs[kr][d] = kvsrc[key*(2*DS_) + DS_ + head*DH_ + d];
        }
        __syncthreads();

        float s[4] = {0.f, 0.f, 0.f, 0.f};
#pragma unroll
        for (int d4 = 0; d4 < 8; d4++) {
            float4 q = *reinterpret_cast<const float4*>(&Qs[r][d4*4]);
#pragma unroll
            for (int kk = 0; kk < 4; kk++) {
                float4 k4 = *reinterpret_cast<const float4*>(&Ks[lane + kk*16][d4*4]);
                s[kk] += q.x*k4.x + q.y*k4.y + q.z*k4.z + q.w*k4.w;
            }
        }
        float tmax = -INFINITY;
#pragma unroll
        for (int kk = 0; kk < 4; kk++) { s[kk] *= SCALE_F; tmax = fmaxf(tmax, s[kk]); }
#pragma unroll
        for (int off = 8; off > 0; off >>= 1)
            tmax = fmaxf(tmax, __shfl_xor_sync(0xffffffffu, tmax, off));
        float mnew = fmaxf(m, tmax);
        float corr = __expf(m - mnew);
        float psum = 0.f;
#pragma unroll
        for (int kk = 0; kk < 4; kk++) {
            float p = __expf(s[kk] - mnew);
            Ps[r][lane + kk*16] = p;
            psum += p;
        }
#pragma unroll
        for (int off = 8; off > 0; off >>= 1)
            psum += __shfl_xor_sync(0xffffffffu, psum, off);
        lsum = lsum * corr + psum;
        m = mnew;
        o0a *= corr; o0b *= corr; o1a *= corr; o1b *= corr;
        __syncwarp();
#pragma unroll
        for (int key = 0; key < 64; key += 2) {
            float p0 = Ps[r][key];
            float p1 = Ps[r][key+1];
            float2 v0 = *reinterpret_cast<const float2*>(&Vs[key][d0]);
            float2 v1 = *reinterpret_cast<const float2*>(&Vs[key+1][d0]);
            o0a += p0*v0.x; o1a += p0*v0.y;
            o0b += p1*v1.x; o1b += p1*v1.y;
        }
    }
    float inv = 1.f / lsum;
    float* dst = &g_att[(q0+r)*DS_ + head*DH_ + d0];
    dst[0] = (o0a + o0b)*inv; dst[1] = (o1a + o1b)*inv;
}

// ---------------- upd = st(sparse) + att@Wo.T + bo ; LIF1 ----------------
__global__ void __launch_bounds__(256)
k_d(int l, int par, const float* __restrict__ Wo, const float* __restrict__ bo) {
    __shared__ __align__(16) float As[16][32];
    __shared__ __align__(16) float Ws[16][32];
    __shared__ short ql[32][128];
    __shared__ int qcnt[32];
    __shared__ int sred[256];
    const float* W = Wo + (size_t)l*DS_*DS_;
    const int tid = threadIdx.x;
    const int row0 = blockIdx.y*32, col0 = blockIdx.x*32;
    const float* hsrc = g_hbuf[l][par];
    float* hdst = g_hbuf[l][1-par];

    // build active lists for 32 rows (8 warps x 4 rows)
    {
        const int wrp = tid >> 5, lane = tid & 31;
#pragma unroll
        for (int rr = 0; rr < 4; rr++) {
            int r = wrp*4 + rr;
            int base = 0;
            const float* hr = hsrc + (size_t)(row0+r)*DS_;
#pragma unroll
            for (int c4 = 0; c4 < 4; c4++) {
                float v = hr[c4*32 + lane];
                unsigned mask = __ballot_sync(0xffffffffu, v != 0.f);
                if (v != 0.f)
                    ql[r][base + __popc(mask & ((1u<<lane)-1u))] = (short)(c4*32 + lane);
                base += __popc(mask);
            }
            if (lane == 0) qcnt[r] = base;
        }
    }

    const int ty = tid >> 4;
    const int tx = tid & 15;
    float acc[2][2] = {};
    for (int k0 = 0; k0 < DS_; k0 += 16) {
        if (tid < 128) {
            int lr = tid >> 2, lk = (tid & 3) << 2;
            float4 av = *reinterpret_cast<const float4*>(g_att + (size_t)(row0+lr)*DS_ + k0 + lk);
            As[lk+0][lr]=av.x; As[lk+1][lr]=av.y; As[lk+2][lr]=av.z; As[lk+3][lr]=av.w;
        } else {
            int t2 = tid - 128;
            int lr = t2 >> 2, lk = (t2 & 3) << 2;
            float4 wv = *reinterpret_cast<const float4*>(W + (size_t)(col0+lr)*DS_ + k0 + lk);
            Ws[lk+0][lr]=wv.x; Ws[lk+1][lr]=wv.y; Ws[lk+2][lr]=wv.z; Ws[lk+3][lr]=wv.w;
        }
        __syncthreads();
#pragma unroll
        for (int kk = 0; kk < 16; kk++) {
            float2 a = *reinterpret_cast<const float2*>(&As[kk][ty*2]);
            float2 w = *reinterpret_cast<const float2*>(&Ws[kk][tx*2]);
            acc[0][0]+=a.x*w.x; acc[0][1]+=a.x*w.y;
            acc[1][0]+=a.y*w.x; acc[1][1]+=a.y*w.y;
        }
        __syncthreads();
    }
    float thr = g_ts[l];
    int spikes = 0;
#pragma unroll
    for (int i = 0; i < 2; i++) {
        int rloc = ty*2 + i;
        int r = row0 + rloc;
        // sparse st for this row, 2 columns
        float s0 = 0.f, s1 = 0.f;
        {
            int cnt = qcnt[rloc];
            const float* at = g_At[l] + col0 + tx*2;
            for (int ii = 0; ii < cnt; ii++) {
                float2 w = *reinterpret_cast<const float2*>(at + (int)ql[rloc][ii]*DS_);
                s0 += w.x; s1 += w.y;
            }
        }
#pragma unroll
        for (int j = 0; j < 2; j++) {
            int c = col0 + tx*2 + j;
            float st = (j == 0) ? s0 : s1;
            float upd = acc[i][j] + bo[l*DS_ + c] + st;
            float v = g_sv[l][r*DS_ + c] * DECAY_F + upd;
            float sp = (v >= thr) ? 1.f : 0.f;
            hdst[r*DS_ + c] = sp;
            g_sv[l][r*DS_ + c] = v * (1.f - sp);
            spikes += (v >= thr) ? 1 : 0;
        }
    }
    sred[tid] = spikes; __syncthreads();
    for (int s = 128; s > 0; s >>= 1) { if (tid < s) sred[tid] += sred[tid+s]; __syncthreads(); }
    if (tid == 0) atomicAdd(&g_cnt1, (unsigned)sred[0]);
}

// ---------------- out_pot = h2@C.T (sparse) ; LIF2 ----------------
__global__ void __launch_bounds__(256)
k_e(int l, int par) {
    __shared__ short ql[8][128];
    __shared__ int qcnt[8];
    __shared__ int sred[256];
    const int tid = threadIdx.x;
    const int row0 = blockIdx.x * 8;
    const float* hnew = g_hbuf[l][1-par];
    // build lists: 8 warps, 1 row each
    {
        const int wrp = tid >> 5, lane = tid & 31;
        int base = 0;
        const float* hr = hnew + (size_t)(row0+wrp)*DS_;
#pragma unroll
        for (int c4 = 0; c4 < 4; c4++) {
            float v = hr[c4*32 + lane];
            unsigned mask = __ballot_sync(0xffffffffu, v != 0.f);
            if (v != 0.f)
                ql[wrp][base + __popc(mask & ((1u<<lane)-1u))] = (short)(c4*32 + lane);
            base += __popc(mask);
        }
        if (lane == 0) qcnt[wrp] = base;
    }
    __syncthreads();
    const int c = tid;
    const float* ct = g_Ct[l] + c;
    float thr = g_to[l];
    int spikes = 0;
#pragma unroll 1
    for (int r = 0; r < 8; r++) {
        float acc = 0.f;
        int cnt = qcnt[r];
        for (int i = 0; i < cnt; i++)
            acc += ct[(int)ql[r][i] * DM_];
        int gi = (row0+r)*DM_ + c;
        float v = g_ov[l][gi] * DECAY_F + acc;
        float sp = (v >= thr) ? 1.f : 0.f;
        g_ov[l][gi] = v * (1.f - sp);
        if (l == 0) g_x[gi] = sp;
        else        g_tsum[gi] += sp * 0.125f;
        spikes += (v >= thr) ? 1 : 0;
    }
    sred[tid] = spikes; __syncthreads();
    for (int s = 128; s > 0; s >>= 1) { if (tid < s) sred[tid] += sred[tid+s]; __syncthreads(); }
    if (tid == 0) atomicAdd(&g_cnt2, (unsigned)sred[0]);
}

// ---------------- logits via bf16 split tensor cores ----------------
__global__ void __launch_bounds__(256)
k_logits_mma(float* __restrict__ out) {
    __shared__ __align__(16) __nv_bfloat16 As[128][48];
    __shared__ __align__(16) __nv_bfloat16 Bs[128][48];
    const int tid = threadIdx.x;
    const int wid = tid >> 5;
    const int wm = wid & 1;
    const int wn = wid >> 1;
    const int row0 = blockIdx.x * 128;
    const int col0 = blockIdx.y * 128;

    wmma::fragment<wmma::accumulator, 16, 16, 16, float> acc[4][2];
#pragma unroll
    for (int i = 0; i < 4; i++)
#pragma unroll
        for (int j = 0; j < 2; j++)
            wmma::fill_fragment(acc[i][j], 0.f);

    const int lr = tid >> 1;
    const int lh = (tid & 1) * 16;

    for (int c = 0; c < 17; c++) {
        const __nv_bfloat16* asrc;
        const __nv_bfloat16* bsrc;
        if (c < 16) {
            int koff = (c & 7) * 32;
            asrc = g_Abf + (size_t)(row0+lr)*DM_ + koff + lh;
            bsrc = ((c < 8) ? g_Whi : g_Wlo) + (size_t)(col0+lr)*DM_ + koff + lh;
        } else {
            asrc = g_Aext + (size_t)(row0+lr)*32 + lh;
            bsrc = g_Bext + (size_t)(col0+lr)*32 + lh;
        }
        uint4 a0 = *reinterpret_cast<const uint4*>(asrc);
        uint4 a1 = *reinterpret_cast<const uint4*>(asrc + 8);
        uint4 b0 = *reinterpret_cast<const uint4*>(bsrc);
        uint4 b1 = *reinterpret_cast<const uint4*>(bsrc + 8);
        __syncthreads();
        *reinterpret_cast<uint4*>(&As[lr][lh])     = a0;
        *reinterpret_cast<uint4*>(&As[lr][lh + 8]) = a1;
        *reinterpret_cast<uint4*>(&Bs[lr][lh])     = b0;
        *reinterpret_cast<uint4*>(&Bs[lr][lh + 8]) = b1;
        __syncthreads();
#pragma unroll
        for (int kk = 0; kk < 32; kk += 16) {
            wmma::fragment<wmma::matrix_a, 16, 16, 16, __nv_bfloat16, wmma::row_major> af[4];
            wmma::fragment<wmma::matrix_b, 16, 16, 16, __nv_bfloat16, wmma::col_major> bf[2];
#pragma unroll
            for (int i = 0; i < 4; i++)
                wmma::load_matrix_sync(af[i], &As[wm*64 + i*16][kk], 48);
#pragma unroll
            for (int j = 0; j < 2; j++)
                wmma::load_matrix_sync(bf[j], &Bs[wn*32 + j*16][kk], 48);
#pragma unroll
            for (int i = 0; i < 4; i++)
#pragma unroll
                for (int j = 0; j < 2; j++)
                    wmma::mma_sync(acc[i][j], af[i], bf[j], acc[i][j]);
        }
    }
#pragma unroll
    for (int i = 0; i < 4; i++)
#pragma unroll
        for (int j = 0; j < 2; j++) {
            size_t r = row0 + wm*64 + i*16;
            size_t cc = col0 + wn*32 + j*16;
            wmma::store_matrix_sync(&out[r*VOC_ + cc], acc[i][j], VOC_, wmma::mem_row_major);
        }
}

// ---------------- launch ----------------
extern "C" void kernel_launch(void* const* d_in, const int* in_sizes, int n_in,
                              void* d_out, int out_size) {
    const int*   ids  = (const int*)d_in[0];
    const float* emb  = (const float*)d_in[1];
    const float* Amat = (const float*)d_in[2];
    const float* Cmat = (const float*)d_in[3];
    const float* Wq   = (const float*)d_in[4];
    const float* bq   = (const float*)d_in[5];
    const float* Wkv  = (const float*)d_in[6];
    const float* bkv  = (const float*)d_in[7];
    const float* Wo   = (const float*)d_in[8];
    const float* bo   = (const float*)d_in[9];
    const float* Wout = (const float*)d_in[10];
    const float* bout = (const float*)d_in[11];
    float* out = (float*)d_out;

    init_kernel<<<256, 256>>>();
    pack_kernel<<<256, 256>>>(Wq, Amat, Cmat, Wkv);
    embed_kernel<<<1024, 256>>>(ids, emb);
    conv_w_kernel<<<2048, 256>>>(Wout, bout);
    k_kv0<<<dim3(4, 16), 512>>>(Wkv, bkv);

    int prev = -1;
    for (int t = 0; t < T_; t++) {
        int par = t & 1;
        for (int l = 0; l < NL_; l++) {
            if (l == 1) k_kv_sp<<<128, 256>>>(bkv);
            k_attn<<<dim3(32, 4), 512>>>(l, prev, par, bq);
            k_d   <<<dim3(4, 32), 256>>>(l, par, Wo, bo);
            k_e   <<<128, 256>>>(l, par);
            prev = l;
        }
    }
    conv_a_kernel<<<1024, 256>>>();
    k_logits_mma<<<dim3(8, 250), 256>>>(out);
}